// round 13
// baseline (speedup 1.0000x reference)
#include <cuda_runtime.h>
#include <math.h>
#include <stdint.h>

#define L_TOK   4096
#define D_MODEL 1536
#define N_HEADS 12
#define H_DIM   128
#define QK_SCALE 0.08838834764831845f  /* 1/sqrt(128) */

// -------- scratch (allocation-free: __device__ globals) --------
__device__ float g_Q[L_TOK * D_MODEL];
__device__ float g_K[L_TOK * D_MODEL];
__device__ float g_V[L_TOK * D_MODEL];   // holds V^T: [D_MODEL][L_TOK]
__device__ float g_A[L_TOK * D_MODEL];   // attention out (tf32-rounded)
__device__ float g_X[L_TOK * D_MODEL];   // x pre-converted to tf32
__device__ float g_W[4 * D_MODEL * D_MODEL]; // wq,wk,wv,wo pre-converted

// =================================================================
// helpers
// =================================================================
__device__ __forceinline__ uint32_t tf32r(float x) {
    uint32_t r;
    asm("cvt.rna.tf32.f32 %0, %1;" : "=r"(r) : "f"(x));
    return r;
}

__device__ __forceinline__ uint32_t smem_u32(const void* p) {
    uint32_t a;
    asm("{ .reg .u64 t; cvta.to.shared.u64 t, %1; cvt.u32.u64 %0, t; }"
        : "=r"(a) : "l"(p));
    return a;
}

__device__ __forceinline__ void cp_async16(uint32_t dst, const float* src) {
    asm volatile("cp.async.cg.shared.global [%0], [%1], 16;"
                 :: "r"(dst), "l"(src) : "memory");
}
#define CP_COMMIT() asm volatile("cp.async.commit_group;" ::: "memory")
#define CP_WAIT1()  asm volatile("cp.async.wait_group 1;" ::: "memory")

// D(m16n8) += A(m16k8,row) * B(k8n8,col)   tf32 inputs, f32 accum
__device__ __forceinline__ void mma_tf32(float* d,
                                         uint32_t a0, uint32_t a1,
                                         uint32_t a2, uint32_t a3,
                                         uint32_t b0, uint32_t b1) {
    asm volatile(
        "mma.sync.aligned.m16n8k8.row.col.f32.tf32.tf32.f32 "
        "{%0,%1,%2,%3}, {%4,%5,%6,%7}, {%8,%9}, {%0,%1,%2,%3};"
        : "+f"(d[0]), "+f"(d[1]), "+f"(d[2]), "+f"(d[3])
        : "r"(a0), "r"(a1), "r"(a2), "r"(a3), "r"(b0), "r"(b1));
}

// =================================================================
// tf32 round pre-pass
// =================================================================
__global__ __launch_bounds__(256) void cvt_tf32_kernel(
    const float* __restrict__ s, float* __restrict__ d)
{
    size_t i = ((size_t)blockIdx.x * 256 + threadIdx.x) * 4;
    float4 v = *(const float4*)(s + i);
    uint4 u = make_uint4(tf32r(v.x), tf32r(v.y), tf32r(v.z), tf32r(v.w));
    *(uint4*)(d + i) = u;
}

// =================================================================
// tf32 mma.sync GEMM, BK=64 stages (128 HMMA/warp between barriers),
// 3-stage cp.async ring. Inputs pre-rounded to tf32.
// C[M,N] = A[M,K] @ W[N,K]^T + bias. CTA 128x128, 8 warps (4Mx2N),
// warp tile 32x64. TRANSPOSED=1 writes C^T [N][M].
// smem/stage: 2 * 128 rows * 68 words = 69.6 KB; 3 stages = 208.9 KB.
// =================================================================
#define SROW 68
#define NSTAGE 3
#define STAGE_WORDS (2 * 128 * SROW)
#define GEMM_SMEM_BYTES (NSTAGE * STAGE_WORDS * 4)

template <int TRANSPOSED>
__global__ __launch_bounds__(256) void mma_gemm_cp(
    const float* __restrict__ A, const float* __restrict__ W,
    const float* __restrict__ bias, float* __restrict__ C,
    int M, int N, int K)
{
    extern __shared__ __align__(16) uint32_t smw[];

    const int tid    = threadIdx.x;
    const int wid    = tid >> 5;
    const int lane   = tid & 31;
    const int warp_m = wid & 3;
    const int warp_n = wid >> 2;
    const int bm     = blockIdx.y * 128;
    const int bn     = blockIdx.x * 128;
    const int g      = lane >> 2;
    const int q      = lane & 3;

    float acc[2][8][4];
#pragma unroll
    for (int mt = 0; mt < 2; mt++)
#pragma unroll
        for (int nt = 0; nt < 8; nt++)
#pragma unroll
            for (int c = 0; c < 4; c++) acc[mt][nt][c] = 0.f;

    // loader mapping: 2 threads per row, 32 consecutive k each (8x 16B)
    const int lrow  = tid >> 1;
    const int lhalf = (tid & 1) * 32;
    const float* Ap = A + (size_t)(bm + lrow) * K + lhalf;
    const float* Wp = W + (size_t)(bn + lrow) * K + lhalf;
    const uint32_t sbase = smem_u32(smw);
    const uint32_t sOffB = ((uint32_t)lrow * SROW + (uint32_t)lhalf) * 4u;

    const int nIter = K / 64;   // 24

    auto issue = [&](int it) {
        const int s = it % NSTAGE;
        const uint32_t aDst = sbase + (uint32_t)s * (STAGE_WORDS * 4u) + sOffB;
        const uint32_t wDst = aDst + 128u * SROW * 4u;
        const float* ag = Ap + it * 64;
        const float* wg = Wp + it * 64;
#pragma unroll
        for (int i = 0; i < 8; i++) {
            cp_async16(aDst + i * 16u, ag + i * 4);
            cp_async16(wDst + i * 16u, wg + i * 4);
        }
    };

    issue(0); CP_COMMIT();
    issue(1); CP_COMMIT();

    const int aBaseM0 = warp_m * 32;
    const int bBaseN  = warp_n * 64;

    for (int it = 0; it < nIter; it++) {
        CP_WAIT1();           // stage `it` landed (stage it+1 may be in flight)
        __syncthreads();      // all warps done with stage it-1's buffer
        if (it + 2 < nIter) issue(it + 2);
        CP_COMMIT();

        const uint32_t* As = smw + (it % NSTAGE) * STAGE_WORDS;
        const uint32_t* Ws = As + 128 * SROW;

#pragma unroll
        for (int ks = 0; ks < 8; ks++) {
            const int kk = ks * 8;
            uint32_t a[2][4];
#pragma unroll
            for (int mt = 0; mt < 2; mt++) {
                const int r = aBaseM0 + mt * 16;
                a[mt][0] = As[(r + g)     * SROW + kk + q];
                a[mt][1] = As[(r + g + 8) * SROW + kk + q];
                a[mt][2] = As[(r + g)     * SROW + kk + q + 4];
                a[mt][3] = As[(r + g + 8) * SROW + kk + q + 4];
            }
#pragma unroll
            for (int nt = 0; nt < 8; nt++) {
                const int c = bBaseN + nt * 8;
                uint32_t b0 = Ws[(c + g) * SROW + kk + q];
                uint32_t b1 = Ws[(c + g) * SROW + kk + q + 4];
                mma_tf32(acc[0][nt], a[0][0], a[0][1], a[0][2], a[0][3], b0, b1);
                mma_tf32(acc[1][nt], a[1][0], a[1][1], a[1][2], a[1][3], b0, b1);
            }
        }
    }

    // epilogue
#pragma unroll
    for (int mt = 0; mt < 2; mt++) {
        const int row0 = bm + aBaseM0 + mt * 16 + g;
#pragma unroll
        for (int nt = 0; nt < 8; nt++) {
            const int col = bn + bBaseN + nt * 8 + q * 2;
            const float2 bb = *(const float2*)&bias[col];
            if (TRANSPOSED) {
                C[(size_t)col       * M + row0]     = acc[mt][nt][0] + bb.x;
                C[(size_t)(col + 1) * M + row0]     = acc[mt][nt][1] + bb.y;
                C[(size_t)col       * M + row0 + 8] = acc[mt][nt][2] + bb.x;
                C[(size_t)(col + 1) * M + row0 + 8] = acc[mt][nt][3] + bb.y;
            } else {
                float2 r0, r1;
                r0.x = acc[mt][nt][0] + bb.x;
                r0.y = acc[mt][nt][1] + bb.y;
                r1.x = acc[mt][nt][2] + bb.x;
                r1.y = acc[mt][nt][3] + bb.y;
                *(float2*)&C[(size_t)row0 * N + col]       = r0;
                *(float2*)&C[(size_t)(row0 + 8) * N + col] = r1;
            }
        }
    }
}

// =================================================================
// Fused full-D RMSNorm + 3-axis RoPE, in-place on g_Q / g_K.
// =================================================================
__global__ __launch_bounds__(256) void norm_rope_kernel(
    const float* __restrict__ gq, const float* __restrict__ gk,
    const float* __restrict__ fcos, const float* __restrict__ fsin)
{
    const int l = blockIdx.x;
    float* row = (blockIdx.y == 0 ? g_Q : g_K) + (size_t)l * D_MODEL;
    const float* g = (blockIdx.y == 0) ? gq : gk;
    const int tid = threadIdx.x;

    float2 v[3];
    float ss = 0.f;
#pragma unroll
    for (int t = 0; t < 3; t++) {
        int p = tid + t * 256;
        v[t] = *(const float2*)&row[2*p];
        ss += v[t].x*v[t].x + v[t].y*v[t].y;
    }
#pragma unroll
    for (int s = 16; s; s >>= 1) ss += __shfl_xor_sync(0xffffffffu, ss, s);

    __shared__ float warp_ss[8];
    __shared__ float inv_s;
    if ((tid & 31) == 0) warp_ss[tid >> 5] = ss;
    __syncthreads();
    if (tid == 0) {
        float tot = 0.f;
#pragma unroll
        for (int i = 0; i < 8; i++) tot += warp_ss[i];
        inv_s = rsqrtf(tot / (float)D_MODEL + 1e-6f);
    }
    __syncthreads();
    const float inv = inv_s;

    const int fi = l >> 10;
    const int hi = (l >> 5) & 31;
    const int wi = l & 31;

#pragma unroll
    for (int t = 0; t < 3; t++) {
        int p = tid + t * 256;
        int c = p & 63;
        int rowi = (c < 22) ? fi : ((c < 43) ? hi : wi);
        float cv = fcos[rowi * 64 + c];
        float sv = fsin[rowi * 64 + c];
        float xr = v[t].x * inv * g[2*p];
        float xi = v[t].y * inv * g[2*p+1];
        float2 o;
        o.x = xr * cv - xi * sv;
        o.y = xr * sv + xi * cv;
        *(float2*)&row[2*p] = o;
    }
}

// =================================================================
// tf32 mma.sync flash attention (validated R10 design).
// =================================================================
#define AKS_OFF 0
#define AVT_OFF (64*132)
#define APS_OFF (64*132 + 128*68)
#define ATT_SMEM_WORDS (64*132 + 2*128*68)
#define ATT_SMEM_BYTES (ATT_SMEM_WORDS * 4)

__global__ __launch_bounds__(256) void attn_mma_kernel(
    const float* __restrict__ Q, const float* __restrict__ K,
    const float* __restrict__ Vt, float* __restrict__ O)
{
    extern __shared__ __align__(16) uint32_t smw[];
    const int tid  = threadIdx.x;
    const int lane = tid & 31;
    const int wid  = tid >> 5;
    const int g    = lane >> 2;
    const int q    = lane & 3;
    const int head = blockIdx.y;
    const int q0   = blockIdx.x * 128;
    const int hoff = head * H_DIM;
    const int mrow = wid * 16;

    // ---- stage Q (pre-scaled, tf32) then lift fragments to regs ----
#pragma unroll
    for (int it = 0; it < 16; it++) {
        int ci = it * 256 + tid;
        int r  = ci >> 5, cq = ci & 31;
        float4 v = *(const float4*)&Q[(size_t)(q0 + r) * D_MODEL + hoff + cq * 4];
        uint4 u = make_uint4(tf32r(v.x * QK_SCALE), tf32r(v.y * QK_SCALE),
                             tf32r(v.z * QK_SCALE), tf32r(v.w * QK_SCALE));
        *(uint4*)&smw[r * 132 + cq * 4] = u;
    }
    __syncthreads();
    uint32_t qa[16][4];
#pragma unroll
    for (int ks = 0; ks < 16; ks++) {
        const int kk = ks * 8;
        qa[ks][0] = smw[(mrow + g)     * 132 + kk + q];
        qa[ks][1] = smw[(mrow + g + 8) * 132 + kk + q];
        qa[ks][2] = smw[(mrow + g)     * 132 + kk + q + 4];
        qa[ks][3] = smw[(mrow + g + 8) * 132 + kk + q + 4];
    }

    uint32_t* Ks  = smw + AKS_OFF;
    uint32_t* Vts = smw + AVT_OFF;
    uint32_t* Ps  = smw + APS_OFF;

    float m0 = -1e30f, m1 = -1e30f, l0 = 0.f, l1 = 0.f;
    float Oa[16][4];
#pragma unroll
    for (int nt = 0; nt < 16; nt++)
#pragma unroll
        for (int c = 0; c < 4; c++) Oa[nt][c] = 0.f;

    for (int kb = 0; kb < L_TOK / 64; kb++) {
        const int k0 = kb * 64;
        __syncthreads();
#pragma unroll
        for (int it = 0; it < 8; it++) {
            int ci = it * 256 + tid;
            int r  = ci >> 5, cq = ci & 31;
            float4 v = *(const float4*)&K[(size_t)(k0 + r) * D_MODEL + hoff + cq * 4];
            *(uint4*)&Ks[r * 132 + cq * 4] =
                make_uint4(tf32r(v.x), tf32r(v.y), tf32r(v.z), tf32r(v.w));
        }
#pragma unroll
        for (int it = 0; it < 8; it++) {
            int ci = it * 256 + tid;
            int r  = ci >> 4, cf = ci & 15;
            float4 v = *(const float4*)&Vt[(size_t)(hoff + r) * L_TOK + k0 + cf * 4];
            *(uint4*)&Vts[r * 68 + cf * 4] =
                make_uint4(tf32r(v.x), tf32r(v.y), tf32r(v.z), tf32r(v.w));
        }
        __syncthreads();

        float s[8][4];
#pragma unroll
        for (int nt = 0; nt < 8; nt++)
#pragma unroll
            for (int c = 0; c < 4; c++) s[nt][c] = 0.f;

#pragma unroll
        for (int ks = 0; ks < 16; ks++) {
            const int kk = ks * 8;
#pragma unroll
            for (int nt = 0; nt < 8; nt++) {
                uint32_t b0 = Ks[(nt * 8 + g) * 132 + kk + q];
                uint32_t b1 = Ks[(nt * 8 + g) * 132 + kk + q + 4];
                mma_tf32(s[nt], qa[ks][0], qa[ks][1], qa[ks][2], qa[ks][3], b0, b1);
            }
        }

        float rm0 = -1e30f, rm1 = -1e30f;
#pragma unroll
        for (int nt = 0; nt < 8; nt++) {
            rm0 = fmaxf(rm0, fmaxf(s[nt][0], s[nt][1]));
            rm1 = fmaxf(rm1, fmaxf(s[nt][2], s[nt][3]));
        }
        rm0 = fmaxf(rm0, __shfl_xor_sync(0xffffffffu, rm0, 1));
        rm0 = fmaxf(rm0, __shfl_xor_sync(0xffffffffu, rm0, 2));
        rm1 = fmaxf(rm1, __shfl_xor_sync(0xffffffffu, rm1, 1));
        rm1 = fmaxf(rm1, __shfl_xor_sync(0xffffffffu, rm1, 2));

        const float mn0 = fmaxf(m0, rm0);
        const float mn1 = fmaxf(m1, rm1);
        const float cr0 = __expf(m0 - mn0);
        const float cr1 = __expf(m1 - mn1);
        m0 = mn0; m1 = mn1;

        float rs0 = 0.f, rs1 = 0.f;
#pragma unroll
        for (int nt = 0; nt < 8; nt++) {
            s[nt][0] = __expf(s[nt][0] - mn0);
            s[nt][1] = __expf(s[nt][1] - mn0);
            s[nt][2] = __expf(s[nt][2] - mn1);
            s[nt][3] = __expf(s[nt][3] - mn1);
            rs0 += s[nt][0] + s[nt][1];
            rs1 += s[nt][2] + s[nt][3];
        }
        rs0 += __shfl_xor_sync(0xffffffffu, rs0, 1);
        rs0 += __shfl_xor_sync(0xffffffffu, rs0, 2);
        rs1 += __shfl_xor_sync(0xffffffffu, rs1, 1);
        rs1 += __shfl_xor_sync(0xffffffffu, rs1, 2);
        l0 = l0 * cr0 + rs0;
        l1 = l1 * cr1 + rs1;

#pragma unroll
        for (int nt = 0; nt < 16; nt++) {
            Oa[nt][0] *= cr0; Oa[nt][1] *= cr0;
            Oa[nt][2] *= cr1; Oa[nt][3] *= cr1;
        }

#pragma unroll
        for (int nt = 0; nt < 8; nt++) {
            *(uint2*)&Ps[(mrow + g)     * 68 + nt * 8 + 2 * q] =
                make_uint2(tf32r(s[nt][0]), tf32r(s[nt][1]));
            *(uint2*)&Ps[(mrow + g + 8) * 68 + nt * 8 + 2 * q] =
                make_uint2(tf32r(s[nt][2]), tf32r(s[nt][3]));
        }
        __syncwarp();

#pragma unroll
        for (int ks = 0; ks < 8; ks++) {
            const int kk = ks * 8;
            uint32_t pa0 = Ps[(mrow + g)     * 68 + kk + q];
            uint32_t pa1 = Ps[(mrow + g + 8) * 68 + kk + q];
            uint32_t pa2 = Ps[(mrow + g)     * 68 + kk + q + 4];
            uint32_t pa3 = Ps[(mrow + g + 8) * 68 + kk + q + 4];
#pragma unroll
            for (int nt = 0; nt < 16; nt++) {
                uint32_t b0 = Vts[(nt * 8 + g) * 68 + kk + q];
                uint32_t b1 = Vts[(nt * 8 + g) * 68 + kk + q + 4];
                mma_tf32(Oa[nt], pa0, pa1, pa2, pa3, b0, b1);
            }
        }
        __syncwarp();
    }

    // ---- epilogue: write tf32-rounded (exact for downstream O-GEMM) ----
    const float i0 = 1.f / l0;
    const float i1 = 1.f / l1;
    const int r0 = q0 + mrow + g;
#pragma unroll
    for (int nt = 0; nt < 16; nt++) {
        const int col = hoff + nt * 8 + 2 * q;
        uint2 w0, w1;
        w0.x = tf32r(Oa[nt][0] * i0); w0.y = tf32r(Oa[nt][1] * i0);
        w1.x = tf32r(Oa[nt][2] * i1); w1.y = tf32r(Oa[nt][3] * i1);
        *(uint2*)&O[(size_t)r0 * D_MODEL + col]       = w0;
        *(uint2*)&O[(size_t)(r0 + 8) * D_MODEL + col] = w1;
    }
}

// =================================================================
// launch
// =================================================================
extern "C" void kernel_launch(void* const* d_in, const int* in_sizes, int n_in,
                              void* d_out, int out_size)
{
    (void)in_sizes; (void)n_in; (void)out_size;
    const float* x    = (const float*)d_in[0];
    const float* wq   = (const float*)d_in[1];
    const float* wk   = (const float*)d_in[2];
    const float* wv   = (const float*)d_in[3];
    const float* wo   = (const float*)d_in[4];
    const float* bq   = (const float*)d_in[5];
    const float* bk   = (const float*)d_in[6];
    const float* bv   = (const float*)d_in[7];
    const float* bo   = (const float*)d_in[8];
    const float* gq   = (const float*)d_in[9];
    const float* gk   = (const float*)d_in[10];
    const float* fcos = (const float*)d_in[11];
    const float* fsin = (const float*)d_in[12];

    float *Qp, *Kp, *Vp, *Ap, *Xp, *Wp;
    cudaGetSymbolAddress((void**)&Qp, g_Q);
    cudaGetSymbolAddress((void**)&Kp, g_K);
    cudaGetSymbolAddress((void**)&Vp, g_V);
    cudaGetSymbolAddress((void**)&Ap, g_A);
    cudaGetSymbolAddress((void**)&Xp, g_X);
    cudaGetSymbolAddress((void**)&Wp, g_W);

    float* Wqc = Wp;
    float* Wkc = Wp + (size_t)D_MODEL * D_MODEL;
    float* Wvc = Wp + 2 * (size_t)D_MODEL * D_MODEL;
    float* Woc = Wp + 3 * (size_t)D_MODEL * D_MODEL;

    cudaFuncSetAttribute(mma_gemm_cp<0>, cudaFuncAttributeMaxDynamicSharedMemorySize,
                         GEMM_SMEM_BYTES);
    cudaFuncSetAttribute(mma_gemm_cp<1>, cudaFuncAttributeMaxDynamicSharedMemorySize,
                         GEMM_SMEM_BYTES);
    cudaFuncSetAttribute(attn_mma_kernel, cudaFuncAttributeMaxDynamicSharedMemorySize,
                         ATT_SMEM_BYTES);

    // pre-convert GEMM inputs to tf32 (rna) once
    const int xBlocks = (L_TOK * D_MODEL) / 1024;        // 6144
    const int wBlocks = (D_MODEL * D_MODEL) / 1024;      // 2304
    cvt_tf32_kernel<<<xBlocks, 256>>>(x, Xp);
    cvt_tf32_kernel<<<wBlocks, 256>>>(wq, Wqc);
    cvt_tf32_kernel<<<wBlocks, 256>>>(wk, Wkc);
    cvt_tf32_kernel<<<wBlocks, 256>>>(wv, Wvc);
    cvt_tf32_kernel<<<wBlocks, 256>>>(wo, Woc);

    dim3 gemm_grid(D_MODEL/128, L_TOK/128);   // (12, 32)

    mma_gemm_cp<0><<<gemm_grid, 256, GEMM_SMEM_BYTES>>>(Xp, Wqc, bq, Qp,
                                                        L_TOK, D_MODEL, D_MODEL);
    mma_gemm_cp<0><<<gemm_grid, 256, GEMM_SMEM_BYTES>>>(Xp, Wkc, bk, Kp,
                                                        L_TOK, D_MODEL, D_MODEL);
    mma_gemm_cp<1><<<gemm_grid, 256, GEMM_SMEM_BYTES>>>(Xp, Wvc, bv, Vp,
                                                        L_TOK, D_MODEL, D_MODEL);

    norm_rope_kernel<<<dim3(L_TOK, 2), 256>>>(gq, gk, fcos, fsin);

    attn_mma_kernel<<<dim3(L_TOK/128, N_HEADS), 256, ATT_SMEM_BYTES>>>(Qp, Kp, Vp, Ap);

    mma_gemm_cp<0><<<gemm_grid, 256, GEMM_SMEM_BYTES>>>(Ap, Woc, bo, (float*)d_out,
                                                        L_TOK, D_MODEL, D_MODEL);
}

// round 14
// speedup vs baseline: 1.1734x; 1.1734x over previous
#include <cuda_runtime.h>
#include <math.h>
#include <stdint.h>

#define L_TOK   4096
#define D_MODEL 1536
#define N_HEADS 12
#define H_DIM   128
#define QK_SCALE 0.08838834764831845f  /* 1/sqrt(128) */

// -------- scratch (allocation-free: __device__ globals) --------
__device__ float g_Q[L_TOK * D_MODEL];
__device__ float g_K[L_TOK * D_MODEL];
__device__ float g_V[L_TOK * D_MODEL];   // holds V^T: [D_MODEL][L_TOK]
__device__ float g_A[L_TOK * D_MODEL];   // attention out (tf32-rounded)
__device__ float g_X[L_TOK * D_MODEL];   // x pre-converted to tf32
__device__ float g_W[4 * D_MODEL * D_MODEL]; // wq,wk,wv,wo pre-converted

// =================================================================
// helpers
// =================================================================
__device__ __forceinline__ uint32_t tf32r(float x) {
    uint32_t r;
    asm("cvt.rna.tf32.f32 %0, %1;" : "=r"(r) : "f"(x));
    return r;
}

__device__ __forceinline__ uint32_t smem_u32(const void* p) {
    uint32_t a;
    asm("{ .reg .u64 t; cvta.to.shared.u64 t, %1; cvt.u32.u64 %0, t; }"
        : "=r"(a) : "l"(p));
    return a;
}

__device__ __forceinline__ void cp_async16(uint32_t dst, const float* src) {
    asm volatile("cp.async.cg.shared.global [%0], [%1], 16;"
                 :: "r"(dst), "l"(src) : "memory");
}
#define CP_COMMIT() asm volatile("cp.async.commit_group;" ::: "memory")
#define CP_WAIT1()  asm volatile("cp.async.wait_group 1;" ::: "memory")

// D(m16n8) += A(m16k8,row) * B(k8n8,col)   tf32 inputs, f32 accum
__device__ __forceinline__ void mma_tf32(float* d,
                                         uint32_t a0, uint32_t a1,
                                         uint32_t a2, uint32_t a3,
                                         uint32_t b0, uint32_t b1) {
    asm volatile(
        "mma.sync.aligned.m16n8k8.row.col.f32.tf32.tf32.f32 "
        "{%0,%1,%2,%3}, {%4,%5,%6,%7}, {%8,%9}, {%0,%1,%2,%3};"
        : "+f"(d[0]), "+f"(d[1]), "+f"(d[2]), "+f"(d[3])
        : "r"(a0), "r"(a1), "r"(a2), "r"(a3), "r"(b0), "r"(b1));
}

// =================================================================
// tf32 round pre-pass
// =================================================================
__global__ __launch_bounds__(256) void cvt_tf32_kernel(
    const float* __restrict__ s, float* __restrict__ d)
{
    size_t i = ((size_t)blockIdx.x * 256 + threadIdx.x) * 4;
    float4 v = *(const float4*)(s + i);
    uint4 u = make_uint4(tf32r(v.x), tf32r(v.y), tf32r(v.z), tf32r(v.w));
    *(uint4*)(d + i) = u;
}

// =================================================================
// tf32 mma.sync multi-region GEMM (R12 mainloop, unchanged math).
// grid.x = nRegions * blocksPerRegion; region r = bx / blocksPerRegion
// selects weight slice Wbase + r*N*K, bias b[r], output o[r].
// Region == transposeRegion writes C^T [N][M] (for V^T).
// CTA 128x128, 8 warps (4Mx2N), BK=32, 3-stage cp.async, smem 108 KB.
// =================================================================
#define SROW 36
#define NSTAGE 3
#define STAGE_WORDS (2 * 128 * SROW)
#define GEMM_SMEM_BYTES (NSTAGE * STAGE_WORDS * 4)

__global__ __launch_bounds__(256) void mma_gemm_multi(
    const float* __restrict__ A, const float* __restrict__ Wbase,
    const float* __restrict__ b0, const float* __restrict__ b1,
    const float* __restrict__ b2,
    float* __restrict__ o0, float* __restrict__ o1, float* __restrict__ o2,
    int M, int N, int K, int blocksPerRegion, int transposeRegion)
{
    extern __shared__ __align__(16) uint32_t smw[];

    const int tid    = threadIdx.x;
    const int wid    = tid >> 5;
    const int lane   = tid & 31;
    const int warp_m = wid & 3;
    const int warp_n = wid >> 2;

    const int region = blockIdx.x / blocksPerRegion;
    const int bn     = (blockIdx.x - region * blocksPerRegion) * 128;
    const int bm     = blockIdx.y * 128;
    const float* W    = Wbase + (size_t)region * N * K;
    const float* bias = (region == 0) ? b0 : (region == 1) ? b1 : b2;
    float*       C    = (region == 0) ? o0 : (region == 1) ? o1 : o2;
    const bool   transposed = (region == transposeRegion);

    const int g = lane >> 2;
    const int q = lane & 3;

    float acc[2][8][4];
#pragma unroll
    for (int mt = 0; mt < 2; mt++)
#pragma unroll
        for (int nt = 0; nt < 8; nt++)
#pragma unroll
            for (int c = 0; c < 4; c++) acc[mt][nt][c] = 0.f;

    // loader mapping: 2 threads per row, 16 consecutive k each (4x 16B)
    const int lrow  = tid >> 1;
    const int lhalf = (tid & 1) * 16;
    const float* Ap = A + (size_t)(bm + lrow) * K + lhalf;
    const float* Wp = W + (size_t)(bn + lrow) * K + lhalf;
    const uint32_t sbase = smem_u32(smw);
    const uint32_t sOffB = ((uint32_t)lrow * SROW + (uint32_t)lhalf) * 4u;

    const int nIter = K / 32;   // 48

    auto issue = [&](int it) {
        const int s = it % NSTAGE;
        const uint32_t aDst = sbase + (uint32_t)s * (STAGE_WORDS * 4u) + sOffB;
        const uint32_t wDst = aDst + 128u * SROW * 4u;
        const float* ag = Ap + it * 32;
        const float* wg = Wp + it * 32;
#pragma unroll
        for (int i = 0; i < 4; i++) {
            cp_async16(aDst + i * 16u, ag + i * 4);
            cp_async16(wDst + i * 16u, wg + i * 4);
        }
    };

    issue(0); CP_COMMIT();
    issue(1); CP_COMMIT();

    const int aBaseM0 = warp_m * 32;
    const int bBaseN  = warp_n * 64;

    for (int it = 0; it < nIter; it++) {
        CP_WAIT1();
        __syncthreads();
        if (it + 2 < nIter) issue(it + 2);
        CP_COMMIT();

        const uint32_t* As = smw + (it % NSTAGE) * STAGE_WORDS;
        const uint32_t* Ws = As + 128 * SROW;

#pragma unroll
        for (int ks = 0; ks < 4; ks++) {
            const int kk = ks * 8;
            uint32_t a[2][4];
#pragma unroll
            for (int mt = 0; mt < 2; mt++) {
                const int r = aBaseM0 + mt * 16;
                a[mt][0] = As[(r + g)     * SROW + kk + q];
                a[mt][1] = As[(r + g + 8) * SROW + kk + q];
                a[mt][2] = As[(r + g)     * SROW + kk + q + 4];
                a[mt][3] = As[(r + g + 8) * SROW + kk + q + 4];
            }
#pragma unroll
            for (int nt = 0; nt < 8; nt++) {
                const int c = bBaseN + nt * 8;
                uint32_t b0r = Ws[(c + g) * SROW + kk + q];
                uint32_t b1r = Ws[(c + g) * SROW + kk + q + 4];
                mma_tf32(acc[0][nt], a[0][0], a[0][1], a[0][2], a[0][3], b0r, b1r);
                mma_tf32(acc[1][nt], a[1][0], a[1][1], a[1][2], a[1][3], b0r, b1r);
            }
        }
    }

    // epilogue
#pragma unroll
    for (int mt = 0; mt < 2; mt++) {
        const int row0 = bm + aBaseM0 + mt * 16 + g;
#pragma unroll
        for (int nt = 0; nt < 8; nt++) {
            const int col = bn + bBaseN + nt * 8 + q * 2;
            const float2 bb = *(const float2*)&bias[col];
            if (transposed) {
                C[(size_t)col       * M + row0]     = acc[mt][nt][0] + bb.x;
                C[(size_t)(col + 1) * M + row0]     = acc[mt][nt][1] + bb.y;
                C[(size_t)col       * M + row0 + 8] = acc[mt][nt][2] + bb.x;
                C[(size_t)(col + 1) * M + row0 + 8] = acc[mt][nt][3] + bb.y;
            } else {
                float2 r0, r1;
                r0.x = acc[mt][nt][0] + bb.x;
                r0.y = acc[mt][nt][1] + bb.y;
                r1.x = acc[mt][nt][2] + bb.x;
                r1.y = acc[mt][nt][3] + bb.y;
                *(float2*)&C[(size_t)row0 * N + col]       = r0;
                *(float2*)&C[(size_t)(row0 + 8) * N + col] = r1;
            }
        }
    }
}

// =================================================================
// Fused full-D RMSNorm + 3-axis RoPE, in-place on g_Q / g_K.
// =================================================================
__global__ __launch_bounds__(256) void norm_rope_kernel(
    const float* __restrict__ gq, const float* __restrict__ gk,
    const float* __restrict__ fcos, const float* __restrict__ fsin)
{
    const int l = blockIdx.x;
    float* row = (blockIdx.y == 0 ? g_Q : g_K) + (size_t)l * D_MODEL;
    const float* g = (blockIdx.y == 0) ? gq : gk;
    const int tid = threadIdx.x;

    float2 v[3];
    float ss = 0.f;
#pragma unroll
    for (int t = 0; t < 3; t++) {
        int p = tid + t * 256;
        v[t] = *(const float2*)&row[2*p];
        ss += v[t].x*v[t].x + v[t].y*v[t].y;
    }
#pragma unroll
    for (int s = 16; s; s >>= 1) ss += __shfl_xor_sync(0xffffffffu, ss, s);

    __shared__ float warp_ss[8];
    __shared__ float inv_s;
    if ((tid & 31) == 0) warp_ss[tid >> 5] = ss;
    __syncthreads();
    if (tid == 0) {
        float tot = 0.f;
#pragma unroll
        for (int i = 0; i < 8; i++) tot += warp_ss[i];
        inv_s = rsqrtf(tot / (float)D_MODEL + 1e-6f);
    }
    __syncthreads();
    const float inv = inv_s;

    const int fi = l >> 10;
    const int hi = (l >> 5) & 31;
    const int wi = l & 31;

#pragma unroll
    for (int t = 0; t < 3; t++) {
        int p = tid + t * 256;
        int c = p & 63;
        int rowi = (c < 22) ? fi : ((c < 43) ? hi : wi);
        float cv = fcos[rowi * 64 + c];
        float sv = fsin[rowi * 64 + c];
        float xr = v[t].x * inv * g[2*p];
        float xi = v[t].y * inv * g[2*p+1];
        float2 o;
        o.x = xr * cv - xi * sv;
        o.y = xr * sv + xi * cv;
        *(float2*)&row[2*p] = o;
    }
}

// =================================================================
// tf32 mma.sync flash attention (validated R10 design).
// =================================================================
#define AKS_OFF 0
#define AVT_OFF (64*132)
#define APS_OFF (64*132 + 128*68)
#define ATT_SMEM_WORDS (64*132 + 2*128*68)
#define ATT_SMEM_BYTES (ATT_SMEM_WORDS * 4)

__global__ __launch_bounds__(256) void attn_mma_kernel(
    const float* __restrict__ Q, const float* __restrict__ K,
    const float* __restrict__ Vt, float* __restrict__ O)
{
    extern __shared__ __align__(16) uint32_t smw[];
    const int tid  = threadIdx.x;
    const int lane = tid & 31;
    const int wid  = tid >> 5;
    const int g    = lane >> 2;
    const int q    = lane & 3;
    const int head = blockIdx.y;
    const int q0   = blockIdx.x * 128;
    const int hoff = head * H_DIM;
    const int mrow = wid * 16;

    // ---- stage Q (pre-scaled, tf32) then lift fragments to regs ----
#pragma unroll
    for (int it = 0; it < 16; it++) {
        int ci = it * 256 + tid;
        int r  = ci >> 5, cq = ci & 31;
        float4 v = *(const float4*)&Q[(size_t)(q0 + r) * D_MODEL + hoff + cq * 4];
        uint4 u = make_uint4(tf32r(v.x * QK_SCALE), tf32r(v.y * QK_SCALE),
                             tf32r(v.z * QK_SCALE), tf32r(v.w * QK_SCALE));
        *(uint4*)&smw[r * 132 + cq * 4] = u;
    }
    __syncthreads();
    uint32_t qa[16][4];
#pragma unroll
    for (int ks = 0; ks < 16; ks++) {
        const int kk = ks * 8;
        qa[ks][0] = smw[(mrow + g)     * 132 + kk + q];
        qa[ks][1] = smw[(mrow + g + 8) * 132 + kk + q];
        qa[ks][2] = smw[(mrow + g)     * 132 + kk + q + 4];
        qa[ks][3] = smw[(mrow + g + 8) * 132 + kk + q + 4];
    }

    uint32_t* Ks  = smw + AKS_OFF;
    uint32_t* Vts = smw + AVT_OFF;
    uint32_t* Ps  = smw + APS_OFF;

    float m0 = -1e30f, m1 = -1e30f, l0 = 0.f, l1 = 0.f;
    float Oa[16][4];
#pragma unroll
    for (int nt = 0; nt < 16; nt++)
#pragma unroll
        for (int c = 0; c < 4; c++) Oa[nt][c] = 0.f;

    for (int kb = 0; kb < L_TOK / 64; kb++) {
        const int k0 = kb * 64;
        __syncthreads();
#pragma unroll
        for (int it = 0; it < 8; it++) {
            int ci = it * 256 + tid;
            int r  = ci >> 5, cq = ci & 31;
            float4 v = *(const float4*)&K[(size_t)(k0 + r) * D_MODEL + hoff + cq * 4];
            *(uint4*)&Ks[r * 132 + cq * 4] =
                make_uint4(tf32r(v.x), tf32r(v.y), tf32r(v.z), tf32r(v.w));
        }
#pragma unroll
        for (int it = 0; it < 8; it++) {
            int ci = it * 256 + tid;
            int r  = ci >> 4, cf = ci & 15;
            float4 v = *(const float4*)&Vt[(size_t)(hoff + r) * L_TOK + k0 + cf * 4];
            *(uint4*)&Vts[r * 68 + cf * 4] =
                make_uint4(tf32r(v.x), tf32r(v.y), tf32r(v.z), tf32r(v.w));
        }
        __syncthreads();

        float s[8][4];
#pragma unroll
        for (int nt = 0; nt < 8; nt++)
#pragma unroll
            for (int c = 0; c < 4; c++) s[nt][c] = 0.f;

#pragma unroll
        for (int ks = 0; ks < 16; ks++) {
            const int kk = ks * 8;
#pragma unroll
            for (int nt = 0; nt < 8; nt++) {
                uint32_t b0 = Ks[(nt * 8 + g) * 132 + kk + q];
                uint32_t b1 = Ks[(nt * 8 + g) * 132 + kk + q + 4];
                mma_tf32(s[nt], qa[ks][0], qa[ks][1], qa[ks][2], qa[ks][3], b0, b1);
            }
        }

        float rm0 = -1e30f, rm1 = -1e30f;
#pragma unroll
        for (int nt = 0; nt < 8; nt++) {
            rm0 = fmaxf(rm0, fmaxf(s[nt][0], s[nt][1]));
            rm1 = fmaxf(rm1, fmaxf(s[nt][2], s[nt][3]));
        }
        rm0 = fmaxf(rm0, __shfl_xor_sync(0xffffffffu, rm0, 1));
        rm0 = fmaxf(rm0, __shfl_xor_sync(0xffffffffu, rm0, 2));
        rm1 = fmaxf(rm1, __shfl_xor_sync(0xffffffffu, rm1, 1));
        rm1 = fmaxf(rm1, __shfl_xor_sync(0xffffffffu, rm1, 2));

        const float mn0 = fmaxf(m0, rm0);
        const float mn1 = fmaxf(m1, rm1);
        const float cr0 = __expf(m0 - mn0);
        const float cr1 = __expf(m1 - mn1);
        m0 = mn0; m1 = mn1;

        float rs0 = 0.f, rs1 = 0.f;
#pragma unroll
        for (int nt = 0; nt < 8; nt++) {
            s[nt][0] = __expf(s[nt][0] - mn0);
            s[nt][1] = __expf(s[nt][1] - mn0);
            s[nt][2] = __expf(s[nt][2] - mn1);
            s[nt][3] = __expf(s[nt][3] - mn1);
            rs0 += s[nt][0] + s[nt][1];
            rs1 += s[nt][2] + s[nt][3];
        }
        rs0 += __shfl_xor_sync(0xffffffffu, rs0, 1);
        rs0 += __shfl_xor_sync(0xffffffffu, rs0, 2);
        rs1 += __shfl_xor_sync(0xffffffffu, rs1, 1);
        rs1 += __shfl_xor_sync(0xffffffffu, rs1, 2);
        l0 = l0 * cr0 + rs0;
        l1 = l1 * cr1 + rs1;

#pragma unroll
        for (int nt = 0; nt < 16; nt++) {
            Oa[nt][0] *= cr0; Oa[nt][1] *= cr0;
            Oa[nt][2] *= cr1; Oa[nt][3] *= cr1;
        }

#pragma unroll
        for (int nt = 0; nt < 8; nt++) {
            *(uint2*)&Ps[(mrow + g)     * 68 + nt * 8 + 2 * q] =
                make_uint2(tf32r(s[nt][0]), tf32r(s[nt][1]));
            *(uint2*)&Ps[(mrow + g + 8) * 68 + nt * 8 + 2 * q] =
                make_uint2(tf32r(s[nt][2]), tf32r(s[nt][3]));
        }
        __syncwarp();

#pragma unroll
        for (int ks = 0; ks < 8; ks++) {
            const int kk = ks * 8;
            uint32_t pa0 = Ps[(mrow + g)     * 68 + kk + q];
            uint32_t pa1 = Ps[(mrow + g + 8) * 68 + kk + q];
            uint32_t pa2 = Ps[(mrow + g)     * 68 + kk + q + 4];
            uint32_t pa3 = Ps[(mrow + g + 8) * 68 + kk + q + 4];
#pragma unroll
            for (int nt = 0; nt < 16; nt++) {
                uint32_t b0 = Vts[(nt * 8 + g) * 68 + kk + q];
                uint32_t b1 = Vts[(nt * 8 + g) * 68 + kk + q + 4];
                mma_tf32(Oa[nt], pa0, pa1, pa2, pa3, b0, b1);
            }
        }
        __syncwarp();
    }

    // ---- epilogue: write tf32-rounded (exact for downstream O-GEMM) ----
    const float i0 = 1.f / l0;
    const float i1 = 1.f / l1;
    const int r0 = q0 + mrow + g;
#pragma unroll
    for (int nt = 0; nt < 16; nt++) {
        const int col = hoff + nt * 8 + 2 * q;
        uint2 w0, w1;
        w0.x = tf32r(Oa[nt][0] * i0); w0.y = tf32r(Oa[nt][1] * i0);
        w1.x = tf32r(Oa[nt][2] * i1); w1.y = tf32r(Oa[nt][3] * i1);
        *(uint2*)&O[(size_t)r0 * D_MODEL + col]       = w0;
        *(uint2*)&O[(size_t)(r0 + 8) * D_MODEL + col] = w1;
    }
}

// =================================================================
// launch
// =================================================================
extern "C" void kernel_launch(void* const* d_in, const int* in_sizes, int n_in,
                              void* d_out, int out_size)
{
    (void)in_sizes; (void)n_in; (void)out_size;
    const float* x    = (const float*)d_in[0];
    const float* wq   = (const float*)d_in[1];
    const float* wk   = (const float*)d_in[2];
    const float* wv   = (const float*)d_in[3];
    const float* wo   = (const float*)d_in[4];
    const float* bq   = (const float*)d_in[5];
    const float* bk   = (const float*)d_in[6];
    const float* bv   = (const float*)d_in[7];
    const float* bo   = (const float*)d_in[8];
    const float* gq   = (const float*)d_in[9];
    const float* gk   = (const float*)d_in[10];
    const float* fcos = (const float*)d_in[11];
    const float* fsin = (const float*)d_in[12];

    float *Qp, *Kp, *Vp, *Ap, *Xp, *Wp;
    cudaGetSymbolAddress((void**)&Qp, g_Q);
    cudaGetSymbolAddress((void**)&Kp, g_K);
    cudaGetSymbolAddress((void**)&Vp, g_V);
    cudaGetSymbolAddress((void**)&Ap, g_A);
    cudaGetSymbolAddress((void**)&Xp, g_X);
    cudaGetSymbolAddress((void**)&Wp, g_W);

    float* Wqc = Wp;                                   // region 0
    float* Woc = Wp + 3 * (size_t)D_MODEL * D_MODEL;   // O-projection slice

    cudaFuncSetAttribute(mma_gemm_multi, cudaFuncAttributeMaxDynamicSharedMemorySize,
                         GEMM_SMEM_BYTES);
    cudaFuncSetAttribute(attn_mma_kernel, cudaFuncAttributeMaxDynamicSharedMemorySize,
                         ATT_SMEM_BYTES);

    // pre-convert GEMM inputs to tf32 (rna) once
    const int xBlocks = (L_TOK * D_MODEL) / 1024;        // 6144
    const int wBlocks = (D_MODEL * D_MODEL) / 1024;      // 2304
    cvt_tf32_kernel<<<xBlocks, 256>>>(x, Xp);
    cvt_tf32_kernel<<<wBlocks, 256>>>(wq, Wqc);
    cvt_tf32_kernel<<<wBlocks, 256>>>(wk, Wp + (size_t)D_MODEL * D_MODEL);
    cvt_tf32_kernel<<<wBlocks, 256>>>(wv, Wp + 2 * (size_t)D_MODEL * D_MODEL);
    cvt_tf32_kernel<<<wBlocks, 256>>>(wo, Woc);

    // fused Q/K/V projection: 3 regions x 12 N-blocks, V region transposed
    dim3 qkv_grid(3 * (D_MODEL / 128), L_TOK / 128);   // (36, 32)
    mma_gemm_multi<<<qkv_grid, 256, GEMM_SMEM_BYTES>>>(
        Xp, Wqc, bq, bk, bv, Qp, Kp, Vp,
        L_TOK, D_MODEL, D_MODEL, D_MODEL / 128, /*transposeRegion=*/2);

    norm_rope_kernel<<<dim3(L_TOK, 2), 256>>>(gq, gk, fcos, fsin);

    attn_mma_kernel<<<dim3(L_TOK/128, N_HEADS), 256, ATT_SMEM_BYTES>>>(Qp, Kp, Vp, Ap);

    // O projection: single region, no transpose
    dim3 o_grid(D_MODEL / 128, L_TOK / 128);           // (12, 32)
    mma_gemm_multi<<<o_grid, 256, GEMM_SMEM_BYTES>>>(
        Ap, Woc, bo, bo, bo, (float*)d_out, (float*)d_out, (float*)d_out,
        L_TOK, D_MODEL, D_MODEL, D_MODEL / 128, /*transposeRegion=*/-1);
}

// round 16
// speedup vs baseline: 1.4999x; 1.2783x over previous
#include <cuda_runtime.h>
#include <cuda_fp16.h>
#include <math.h>
#include <stdint.h>

#define L_TOK   4096
#define D_MODEL 1536
#define N_HEADS 12
#define H_DIM   128
#define QK_SCALE 0.08838834764831845f  /* 1/sqrt(128) */

// -------- scratch (allocation-free: __device__ globals) --------
__device__ float  g_Q[L_TOK * D_MODEL];
__device__ float  g_K[L_TOK * D_MODEL];
__device__ float  g_V[L_TOK * D_MODEL];          // V^T: [D_MODEL][L_TOK]
__device__ __half g_Ah[L_TOK * D_MODEL];         // attention out (fp16)
__device__ __half g_Xh[L_TOK * D_MODEL];         // x in fp16
__device__ __half g_Wh[4 * D_MODEL * D_MODEL];   // wq,wk,wv,wo in fp16

// =================================================================
// helpers
// =================================================================
__device__ __forceinline__ uint32_t tf32r(float x) {
    uint32_t r;
    asm("cvt.rna.tf32.f32 %0, %1;" : "=r"(r) : "f"(x));
    return r;
}

__device__ __forceinline__ uint32_t smem_u32(const void* p) {
    uint32_t a;
    asm("{ .reg .u64 t; cvta.to.shared.u64 t, %1; cvt.u32.u64 %0, t; }"
        : "=r"(a) : "l"(p));
    return a;
}

__device__ __forceinline__ void cp_async16(uint32_t dst, const void* src) {
    asm volatile("cp.async.cg.shared.global [%0], [%1], 16;"
                 :: "r"(dst), "l"(src) : "memory");
}
#define CP_COMMIT() asm volatile("cp.async.commit_group;" ::: "memory")
#define CP_WAIT1()  asm volatile("cp.async.wait_group 1;" ::: "memory")

// tf32: D(m16n8) += A(m16k8) * B(k8n8)
__device__ __forceinline__ void mma_tf32(float* d,
                                         uint32_t a0, uint32_t a1,
                                         uint32_t a2, uint32_t a3,
                                         uint32_t b0, uint32_t b1) {
    asm volatile(
        "mma.sync.aligned.m16n8k8.row.col.f32.tf32.tf32.f32 "
        "{%0,%1,%2,%3}, {%4,%5,%6,%7}, {%8,%9}, {%0,%1,%2,%3};"
        : "+f"(d[0]), "+f"(d[1]), "+f"(d[2]), "+f"(d[3])
        : "r"(a0), "r"(a1), "r"(a2), "r"(a3), "r"(b0), "r"(b1));
}

// fp16: D(m16n8,f32) += A(m16k16,f16) * B(k16n8,f16)
__device__ __forceinline__ void mma_f16(float* d,
                                        uint32_t a0, uint32_t a1,
                                        uint32_t a2, uint32_t a3,
                                        uint32_t b0, uint32_t b1) {
    asm volatile(
        "mma.sync.aligned.m16n8k16.row.col.f32.f16.f16.f32 "
        "{%0,%1,%2,%3}, {%4,%5,%6,%7}, {%8,%9}, {%0,%1,%2,%3};"
        : "+f"(d[0]), "+f"(d[1]), "+f"(d[2]), "+f"(d[3])
        : "r"(a0), "r"(a1), "r"(a2), "r"(a3), "r"(b0), "r"(b1));
}

// =================================================================
// float -> fp16 pre-pass (8 elements/thread)
// =================================================================
__global__ __launch_bounds__(256) void cvt_f16_kernel(
    const float* __restrict__ s, __half* __restrict__ d)
{
    size_t i = ((size_t)blockIdx.x * 256 + threadIdx.x) * 8;
    float4 v0 = *(const float4*)(s + i);
    float4 v1 = *(const float4*)(s + i + 4);
    __half2 h0 = __floats2half2_rn(v0.x, v0.y);
    __half2 h1 = __floats2half2_rn(v0.z, v0.w);
    __half2 h2 = __floats2half2_rn(v1.x, v1.y);
    __half2 h3 = __floats2half2_rn(v1.z, v1.w);
    uint4 u;
    u.x = *reinterpret_cast<uint32_t*>(&h0);
    u.y = *reinterpret_cast<uint32_t*>(&h1);
    u.z = *reinterpret_cast<uint32_t*>(&h2);
    u.w = *reinterpret_cast<uint32_t*>(&h3);
    *(uint4*)(d + i) = u;
}

// =================================================================
// fp16 mma.sync multi-region GEMM.
// C[M,N] = A[M,K] @ W[N,K]^T + bias (A,W fp16; C,bias fp32).
// CTA 128x128, 8 warps (4Mx2N), warp tile 32x64, BK=64 halves/stage,
// 3-stage cp.async ring (same 108 KB smem / stride-36-word banking
// as the validated tf32 kernel — rows are 64 halves + 8 pad).
// grid.x = nRegions * blocksPerRegion; region picks W slice/bias/out.
// Region == transposeRegion writes C^T [N][M] (for V^T).
// =================================================================
#define SROW 36                       /* words per row (64 halves + pad) */
#define NSTAGE 3
#define STAGE_WORDS (2 * 128 * SROW)
#define GEMM_SMEM_BYTES (NSTAGE * STAGE_WORDS * 4)

__global__ __launch_bounds__(256) void mma_gemm_f16(
    const __half* __restrict__ A, const __half* __restrict__ Wbase,
    const float* __restrict__ b0, const float* __restrict__ b1,
    const float* __restrict__ b2,
    float* __restrict__ o0, float* __restrict__ o1, float* __restrict__ o2,
    int M, int N, int K, int blocksPerRegion, int transposeRegion)
{
    extern __shared__ __align__(16) uint32_t smw[];

    const int tid    = threadIdx.x;
    const int wid    = tid >> 5;
    const int lane   = tid & 31;
    const int warp_m = wid & 3;
    const int warp_n = wid >> 2;

    const int region = blockIdx.x / blocksPerRegion;
    const int bn     = (blockIdx.x - region * blocksPerRegion) * 128;
    const int bm     = blockIdx.y * 128;
    const __half* W   = Wbase + (size_t)region * N * K;
    const float* bias = (region == 0) ? b0 : (region == 1) ? b1 : b2;
    float*       C    = (region == 0) ? o0 : (region == 1) ? o1 : o2;
    const bool   transposed = (region == transposeRegion);

    const int g = lane >> 2;
    const int q = lane & 3;

    float acc[2][8][4];
#pragma unroll
    for (int mt = 0; mt < 2; mt++)
#pragma unroll
        for (int nt = 0; nt < 8; nt++)
#pragma unroll
            for (int c = 0; c < 4; c++) acc[mt][nt][c] = 0.f;

    // loader: 2 threads/row, 32 consecutive halves (64 B = 4x16B) each
    const int lrow  = tid >> 1;
    const int lhalf = (tid & 1) * 32;
    const __half* Ap = A + (size_t)(bm + lrow) * K + lhalf;
    const __half* Wp = W + (size_t)(bn + lrow) * K + lhalf;
    const uint32_t sbase = smem_u32(smw);
    const uint32_t sOffB = ((uint32_t)lrow * SROW + (uint32_t)(tid & 1) * 16) * 4u;

    const int nIter = K / 64;   // 24

    auto issue = [&](int it) {
        const int s = it % NSTAGE;
        const uint32_t aDst = sbase + (uint32_t)s * (STAGE_WORDS * 4u) + sOffB;
        const uint32_t wDst = aDst + 128u * SROW * 4u;
        const __half* ag = Ap + it * 64;
        const __half* wg = Wp + it * 64;
#pragma unroll
        for (int i = 0; i < 4; i++) {
            cp_async16(aDst + i * 16u, ag + i * 8);
            cp_async16(wDst + i * 16u, wg + i * 8);
        }
    };

    issue(0); CP_COMMIT();
    issue(1); CP_COMMIT();

    const int aBaseM0 = warp_m * 32;
    const int bBaseN  = warp_n * 64;

    for (int it = 0; it < nIter; it++) {
        CP_WAIT1();
        __syncthreads();
        if (it + 2 < nIter) issue(it + 2);
        CP_COMMIT();

        const uint32_t* As = smw + (it % NSTAGE) * STAGE_WORDS;
        const uint32_t* Ws = As + 128 * SROW;

        // 4 k16-steps per stage; word offset kw = ks*8 within the row.
        // a0=(row g,   k 2q..2q+1)  -> word kw+q     a2=(row g,   k 2q+8..9) -> kw+q+4
        // a1=(row g+8, ...)=kw+q               a3 = kw+q+4 (row g+8)
        // b0=(n g, k 2q..2q+1) -> kw+q          b1=(n g, k 2q+8..9) -> kw+q+4
#pragma unroll
        for (int ks = 0; ks < 4; ks++) {
            const int kw = ks * 8;
            uint32_t a[2][4];
#pragma unroll
            for (int mt = 0; mt < 2; mt++) {
                const int r = aBaseM0 + mt * 16;
                a[mt][0] = As[(r + g)     * SROW + kw + q];
                a[mt][1] = As[(r + g + 8) * SROW + kw + q];
                a[mt][2] = As[(r + g)     * SROW + kw + q + 4];
                a[mt][3] = As[(r + g + 8) * SROW + kw + q + 4];
            }
#pragma unroll
            for (int nt = 0; nt < 8; nt++) {
                const int c = bBaseN + nt * 8;
                uint32_t b0r = Ws[(c + g) * SROW + kw + q];
                uint32_t b1r = Ws[(c + g) * SROW + kw + q + 4];
                mma_f16(acc[0][nt], a[0][0], a[0][1], a[0][2], a[0][3], b0r, b1r);
                mma_f16(acc[1][nt], a[1][0], a[1][1], a[1][2], a[1][3], b0r, b1r);
            }
        }
    }

    // epilogue (D layout identical to k8 variant)
#pragma unroll
    for (int mt = 0; mt < 2; mt++) {
        const int row0 = bm + aBaseM0 + mt * 16 + g;
#pragma unroll
        for (int nt = 0; nt < 8; nt++) {
            const int col = bn + bBaseN + nt * 8 + q * 2;
            const float2 bb = *(const float2*)&bias[col];
            if (transposed) {
                C[(size_t)col       * M + row0]     = acc[mt][nt][0] + bb.x;
                C[(size_t)(col + 1) * M + row0]     = acc[mt][nt][1] + bb.y;
                C[(size_t)col       * M + row0 + 8] = acc[mt][nt][2] + bb.x;
                C[(size_t)(col + 1) * M + row0 + 8] = acc[mt][nt][3] + bb.y;
            } else {
                float2 r0, r1;
                r0.x = acc[mt][nt][0] + bb.x;
                r0.y = acc[mt][nt][1] + bb.y;
                r1.x = acc[mt][nt][2] + bb.x;
                r1.y = acc[mt][nt][3] + bb.y;
                *(float2*)&C[(size_t)row0 * N + col]       = r0;
                *(float2*)&C[(size_t)(row0 + 8) * N + col] = r1;
            }
        }
    }
}

// =================================================================
// Fused full-D RMSNorm + 3-axis RoPE, in-place on g_Q / g_K.
// =================================================================
__global__ __launch_bounds__(256) void norm_rope_kernel(
    const float* __restrict__ gq, const float* __restrict__ gk,
    const float* __restrict__ fcos, const float* __restrict__ fsin)
{
    const int l = blockIdx.x;
    float* row = (blockIdx.y == 0 ? g_Q : g_K) + (size_t)l * D_MODEL;
    const float* g = (blockIdx.y == 0) ? gq : gk;
    const int tid = threadIdx.x;

    float2 v[3];
    float ss = 0.f;
#pragma unroll
    for (int t = 0; t < 3; t++) {
        int p = tid + t * 256;
        v[t] = *(const float2*)&row[2*p];
        ss += v[t].x*v[t].x + v[t].y*v[t].y;
    }
#pragma unroll
    for (int s = 16; s; s >>= 1) ss += __shfl_xor_sync(0xffffffffu, ss, s);

    __shared__ float warp_ss[8];
    __shared__ float inv_s;
    if ((tid & 31) == 0) warp_ss[tid >> 5] = ss;
    __syncthreads();
    if (tid == 0) {
        float tot = 0.f;
#pragma unroll
        for (int i = 0; i < 8; i++) tot += warp_ss[i];
        inv_s = rsqrtf(tot / (float)D_MODEL + 1e-6f);
    }
    __syncthreads();
    const float inv = inv_s;

    const int fi = l >> 10;
    const int hi = (l >> 5) & 31;
    const int wi = l & 31;

#pragma unroll
    for (int t = 0; t < 3; t++) {
        int p = tid + t * 256;
        int c = p & 63;
        int rowi = (c < 22) ? fi : ((c < 43) ? hi : wi);
        float cv = fcos[rowi * 64 + c];
        float sv = fsin[rowi * 64 + c];
        float xr = v[t].x * inv * g[2*p];
        float xi = v[t].y * inv * g[2*p+1];
        float2 o;
        o.x = xr * cv - xi * sv;
        o.y = xr * sv + xi * cv;
        *(float2*)&row[2*p] = o;
    }
}

// =================================================================
// tf32 mma.sync flash attention (validated R10 design, unchanged
// mainloop). Epilogue writes fp16 directly for the O-projection.
// =================================================================
#define AKS_OFF 0
#define AVT_OFF (64*132)
#define APS_OFF (64*132 + 128*68)
#define ATT_SMEM_WORDS (64*132 + 2*128*68)
#define ATT_SMEM_BYTES (ATT_SMEM_WORDS * 4)

__global__ __launch_bounds__(256) void attn_mma_kernel(
    const float* __restrict__ Q, const float* __restrict__ K,
    const float* __restrict__ Vt, __half* __restrict__ O)
{
    extern __shared__ __align__(16) uint32_t smw[];
    const int tid  = threadIdx.x;
    const int lane = tid & 31;
    const int wid  = tid >> 5;
    const int g    = lane >> 2;
    const int q    = lane & 3;
    const int head = blockIdx.y;
    const int q0   = blockIdx.x * 128;
    const int hoff = head * H_DIM;
    const int mrow = wid * 16;

    // ---- stage Q (pre-scaled, tf32) then lift fragments to regs ----
#pragma unroll
    for (int it = 0; it < 16; it++) {
        int ci = it * 256 + tid;
        int r  = ci >> 5, cq = ci & 31;
        float4 v = *(const float4*)&Q[(size_t)(q0 + r) * D_MODEL + hoff + cq * 4];
        uint4 u = make_uint4(tf32r(v.x * QK_SCALE), tf32r(v.y * QK_SCALE),
                             tf32r(v.z * QK_SCALE), tf32r(v.w * QK_SCALE));
        *(uint4*)&smw[r * 132 + cq * 4] = u;
    }
    __syncthreads();
    uint32_t qa[16][4];
#pragma unroll
    for (int ks = 0; ks < 16; ks++) {
        const int kk = ks * 8;
        qa[ks][0] = smw[(mrow + g)     * 132 + kk + q];
        qa[ks][1] = smw[(mrow + g + 8) * 132 + kk + q];
        qa[ks][2] = smw[(mrow + g)     * 132 + kk + q + 4];
        qa[ks][3] = smw[(mrow + g + 8) * 132 + kk + q + 4];
    }

    uint32_t* Ks  = smw + AKS_OFF;
    uint32_t* Vts = smw + AVT_OFF;
    uint32_t* Ps  = smw + APS_OFF;

    float m0 = -1e30f, m1 = -1e30f, l0 = 0.f, l1 = 0.f;
    float Oa[16][4];
#pragma unroll
    for (int nt = 0; nt < 16; nt++)
#pragma unroll
        for (int c = 0; c < 4; c++) Oa[nt][c] = 0.f;

    for (int kb = 0; kb < L_TOK / 64; kb++) {
        const int k0 = kb * 64;
        __syncthreads();
#pragma unroll
        for (int it = 0; it < 8; it++) {
            int ci = it * 256 + tid;
            int r  = ci >> 5, cq = ci & 31;
            float4 v = *(const float4*)&K[(size_t)(k0 + r) * D_MODEL + hoff + cq * 4];
            *(uint4*)&Ks[r * 132 + cq * 4] =
                make_uint4(tf32r(v.x), tf32r(v.y), tf32r(v.z), tf32r(v.w));
        }
#pragma unroll
        for (int it = 0; it < 8; it++) {
            int ci = it * 256 + tid;
            int r  = ci >> 4, cf = ci & 15;
            float4 v = *(const float4*)&Vt[(size_t)(hoff + r) * L_TOK + k0 + cf * 4];
            *(uint4*)&Vts[r * 68 + cf * 4] =
                make_uint4(tf32r(v.x), tf32r(v.y), tf32r(v.z), tf32r(v.w));
        }
        __syncthreads();

        float s[8][4];
#pragma unroll
        for (int nt = 0; nt < 8; nt++)
#pragma unroll
            for (int c = 0; c < 4; c++) s[nt][c] = 0.f;

#pragma unroll
        for (int ks = 0; ks < 16; ks++) {
            const int kk = ks * 8;
#pragma unroll
            for (int nt = 0; nt < 8; nt++) {
                uint32_t b0 = Ks[(nt * 8 + g) * 132 + kk + q];
                uint32_t b1 = Ks[(nt * 8 + g) * 132 + kk + q + 4];
                mma_tf32(s[nt], qa[ks][0], qa[ks][1], qa[ks][2], qa[ks][3], b0, b1);
            }
        }

        float rm0 = -1e30f, rm1 = -1e30f;
#pragma unroll
        for (int nt = 0; nt < 8; nt++) {
            rm0 = fmaxf(rm0, fmaxf(s[nt][0], s[nt][1]));
            rm1 = fmaxf(rm1, fmaxf(s[nt][2], s[nt][3]));
        }
        rm0 = fmaxf(rm0, __shfl_xor_sync(0xffffffffu, rm0, 1));
        rm0 = fmaxf(rm0, __shfl_xor_sync(0xffffffffu, rm0, 2));
        rm1 = fmaxf(rm1, __shfl_xor_sync(0xffffffffu, rm1, 1));
        rm1 = fmaxf(rm1, __shfl_xor_sync(0xffffffffu, rm1, 2));

        const float mn0 = fmaxf(m0, rm0);
        const float mn1 = fmaxf(m1, rm1);
        const float cr0 = __expf(m0 - mn0);
        const float cr1 = __expf(m1 - mn1);
        m0 = mn0; m1 = mn1;

        float rs0 = 0.f, rs1 = 0.f;
#pragma unroll
        for (int nt = 0; nt < 8; nt++) {
            s[nt][0] = __expf(s[nt][0] - mn0);
            s[nt][1] = __expf(s[nt][1] - mn0);
            s[nt][2] = __expf(s[nt][2] - mn1);
            s[nt][3] = __expf(s[nt][3] - mn1);
            rs0 += s[nt][0] + s[nt][1];
            rs1 += s[nt][2] + s[nt][3];
        }
        rs0 += __shfl_xor_sync(0xffffffffu, rs0, 1);
        rs0 += __shfl_xor_sync(0xffffffffu, rs0, 2);
        rs1 += __shfl_xor_sync(0xffffffffu, rs1, 1);
        rs1 += __shfl_xor_sync(0xffffffffu, rs1, 2);
        l0 = l0 * cr0 + rs0;
        l1 = l1 * cr1 + rs1;

#pragma unroll
        for (int nt = 0; nt < 16; nt++) {
            Oa[nt][0] *= cr0; Oa[nt][1] *= cr0;
            Oa[nt][2] *= cr1; Oa[nt][3] *= cr1;
        }

#pragma unroll
        for (int nt = 0; nt < 8; nt++) {
            *(uint2*)&Ps[(mrow + g)     * 68 + nt * 8 + 2 * q] =
                make_uint2(tf32r(s[nt][0]), tf32r(s[nt][1]));
            *(uint2*)&Ps[(mrow + g + 8) * 68 + nt * 8 + 2 * q] =
                make_uint2(tf32r(s[nt][2]), tf32r(s[nt][3]));
        }
        __syncwarp();

#pragma unroll
        for (int ks = 0; ks < 8; ks++) {
            const int kk = ks * 8;
            uint32_t pa0 = Ps[(mrow + g)     * 68 + kk + q];
            uint32_t pa1 = Ps[(mrow + g + 8) * 68 + kk + q];
            uint32_t pa2 = Ps[(mrow + g)     * 68 + kk + q + 4];
            uint32_t pa3 = Ps[(mrow + g + 8) * 68 + kk + q + 4];
#pragma unroll
            for (int nt = 0; nt < 16; nt++) {
                uint32_t b0 = Vts[(nt * 8 + g) * 68 + kk + q];
                uint32_t b1 = Vts[(nt * 8 + g) * 68 + kk + q + 4];
                mma_tf32(Oa[nt], pa0, pa1, pa2, pa3, b0, b1);
            }
        }
        __syncwarp();
    }

    // ---- epilogue: write fp16 for the downstream O-projection GEMM ----
    const float i0 = 1.f / l0;
    const float i1 = 1.f / l1;
    const int r0 = q0 + mrow + g;
#pragma unroll
    for (int nt = 0; nt < 16; nt++) {
        const int col = hoff + nt * 8 + 2 * q;
        __half2 h0 = __floats2half2_rn(Oa[nt][0] * i0, Oa[nt][1] * i0);
        __half2 h1 = __floats2half2_rn(Oa[nt][2] * i1, Oa[nt][3] * i1);
        *(__half2*)&O[(size_t)r0 * D_MODEL + col]       = h0;
        *(__half2*)&O[(size_t)(r0 + 8) * D_MODEL + col] = h1;
    }
}

// =================================================================
// launch
// =================================================================
extern "C" void kernel_launch(void* const* d_in, const int* in_sizes, int n_in,
                              void* d_out, int out_size)
{
    (void)in_sizes; (void)n_in; (void)out_size;
    const float* x    = (const float*)d_in[0];
    const float* wq   = (const float*)d_in[1];
    const float* wk   = (const float*)d_in[2];
    const float* wv   = (const float*)d_in[3];
    const float* wo   = (const float*)d_in[4];
    const float* bq   = (const float*)d_in[5];
    const float* bk   = (const float*)d_in[6];
    const float* bv   = (const float*)d_in[7];
    const float* bo   = (const float*)d_in[8];
    const float* gq   = (const float*)d_in[9];
    const float* gk   = (const float*)d_in[10];
    const float* fcos = (const float*)d_in[11];
    const float* fsin = (const float*)d_in[12];

    float  *Qp, *Kp, *Vp;
    __half *Ahp, *Xhp, *Whp;
    cudaGetSymbolAddress((void**)&Qp,  g_Q);
    cudaGetSymbolAddress((void**)&Kp,  g_K);
    cudaGetSymbolAddress((void**)&Vp,  g_V);
    cudaGetSymbolAddress((void**)&Ahp, g_Ah);
    cudaGetSymbolAddress((void**)&Xhp, g_Xh);
    cudaGetSymbolAddress((void**)&Whp, g_Wh);

    __half* Wqh = Whp;                                   // region 0
    __half* Woh = Whp + 3 * (size_t)D_MODEL * D_MODEL;   // O-projection

    cudaFuncSetAttribute(mma_gemm_f16, cudaFuncAttributeMaxDynamicSharedMemorySize,
                         GEMM_SMEM_BYTES);
    cudaFuncSetAttribute(attn_mma_kernel, cudaFuncAttributeMaxDynamicSharedMemorySize,
                         ATT_SMEM_BYTES);

    // pre-convert GEMM inputs to fp16 once
    const int xBlocks = (L_TOK * D_MODEL) / 2048;        // 3072
    const int wBlocks = (D_MODEL * D_MODEL) / 2048;      // 1152
    cvt_f16_kernel<<<xBlocks, 256>>>(x, Xhp);
    cvt_f16_kernel<<<wBlocks, 256>>>(wq, Wqh);
    cvt_f16_kernel<<<wBlocks, 256>>>(wk, Whp + (size_t)D_MODEL * D_MODEL);
    cvt_f16_kernel<<<wBlocks, 256>>>(wv, Whp + 2 * (size_t)D_MODEL * D_MODEL);
    cvt_f16_kernel<<<wBlocks, 256>>>(wo, Woh);

    // fused Q/K/V projection: 3 regions x 12 N-blocks, V region transposed
    dim3 qkv_grid(3 * (D_MODEL / 128), L_TOK / 128);     // (36, 32)
    mma_gemm_f16<<<qkv_grid, 256, GEMM_SMEM_BYTES>>>(
        Xhp, Wqh, bq, bk, bv, Qp, Kp, Vp,
        L_TOK, D_MODEL, D_MODEL, D_MODEL / 128, /*transposeRegion=*/2);

    norm_rope_kernel<<<dim3(L_TOK, 2), 256>>>(gq, gk, fcos, fsin);

    attn_mma_kernel<<<dim3(L_TOK/128, N_HEADS), 256, ATT_SMEM_BYTES>>>(Qp, Kp, Vp, Ahp);

    // O projection: single region, no transpose
    dim3 o_grid(D_MODEL / 128, L_TOK / 128);             // (12, 32)
    mma_gemm_f16<<<o_grid, 256, GEMM_SMEM_BYTES>>>(
        Ahp, Woh, bo, bo, bo, (float*)d_out, (float*)d_out, (float*)d_out,
        L_TOK, D_MODEL, D_MODEL, D_MODEL / 128, /*transposeRegion=*/-1);
}